// round 11
// baseline (speedup 1.0000x reference)
#include <cuda_runtime.h>
#include <cstdint>

// out[dst[e]] += edge_attr[e] * x[src[e]],  D=64 f32, indices int32.
// History: R2 scatter 58us (REDG-bound). R4/R6 bucket+gather 47.6us. R7 fp16
// 46.8us. R8/R9 inner-loop variants regressed (R7 gather loop = local
// optimum). R10 fused persistent kernel + grid barrier: 45.5us.
// R11: drop the fp16 conversion entirely -- R4-vs-R7 showed the gather is
// issue/latency bound, not byte bound, so fp16 bought nothing while costing
// 38MB of traffic and 1/4 of the phase-1 blocks. Now ALL blocks fill in
// phase 1 (fill ~4/3 faster), and the gather reads fp32 x directly
// (float2/lane = one coalesced 256B row per warp). rel_err back to ~1e-7.

#define BUCKET_CAP 192           // Poisson(40) over 25K bins: max ~85
#define MAX_CB     32768
#define MAX_NODES  131072

__device__ int      g_counts[MAX_CB];                        // zero-init, self-resetting
__device__ int2     g_bucket[(size_t)MAX_CB * BUCKET_CAP];   // {src, attr bits}
__device__ unsigned g_bar;                                   // monotonic barrier counter

// ---------------- helpers ----------------
__device__ __forceinline__ void _fill_one(int s, int d, float w,
                                          int n_coarse, int n_nodes) {
    if ((unsigned)d >= (unsigned)n_coarse) return;
    if ((unsigned)s >= (unsigned)n_nodes) { s = 0; w = 0.f; }
    int pos = atomicAdd(&g_counts[d], 1);
    if (pos < BUCKET_CAP)
        g_bucket[(unsigned)d * BUCKET_CAP + pos] = make_int2(s, __float_as_int(w));
    // overflow: true total stays in g_counts; gather rescans exactly.
}

__device__ __forceinline__ void _acc2(float2& acc, const float2* __restrict__ x2,
                                      unsigned s, float wt, unsigned lane) {
    float2 v = x2[s * 32u + lane];
    acc.x = fmaf(wt, v.x, acc.x);
    acc.y = fmaf(wt, v.y, acc.y);
}

// Replay-safe grid barrier: counter only ever increments; each call's blocks
// wait for the next multiple of gridDim.x. Requires all blocks resident.
__device__ __forceinline__ void _grid_barrier(unsigned nB) {
    __threadfence();
    __syncthreads();
    if (threadIdx.x == 0) {
        unsigned arrive;
        asm volatile("atom.add.release.gpu.u32 %0, [%1], 1;"
                     : "=r"(arrive) : "l"(&g_bar) : "memory");
        arrive += 1;
        unsigned target = ((arrive - 1) / nB + 1) * nB;
        unsigned cur;
        do {
            asm volatile("ld.acquire.gpu.u32 %0, [%1];"
                         : "=r"(cur) : "l"(&g_bar) : "memory");
        } while (cur < target);
    }
    __syncthreads();
}

// ---------------- fused persistent kernel ----------------
__global__ void __launch_bounds__(256, 6)
_fused_kernel(const float2* __restrict__ x2,     // x as [n_nodes, 32] float2
              const int* __restrict__ src, const int* __restrict__ dst,
              const float* __restrict__ attr,
              float2* __restrict__ out2,          // [n_coarse, 32] float2
              int num_edges, int n_coarse, int n_nodes, int vec_ok) {
    const unsigned nB  = gridDim.x;
    const unsigned bid = blockIdx.x;
    const unsigned tid = threadIdx.x;

    // ---- phase 1: bucket fill, all blocks, 4 edges/thread ----
    {
        int nchunks = (num_edges + 3) / 4;
        for (int ch = bid * 256 + tid; ch < nchunks; ch += nB * 256) {
            int base = ch * 4;
            if (vec_ok && base + 4 <= num_edges) {
                int4   s4 = *(const int4*)(src + base);
                int4   d4 = *(const int4*)(dst + base);
                float4 w4 = *(const float4*)(attr + base);
                _fill_one(s4.x, d4.x, w4.x, n_coarse, n_nodes);
                _fill_one(s4.y, d4.y, w4.y, n_coarse, n_nodes);
                _fill_one(s4.z, d4.z, w4.z, n_coarse, n_nodes);
                _fill_one(s4.w, d4.w, w4.w, n_coarse, n_nodes);
            } else {
                int m = min(4, num_edges - base);
                for (int k = 0; k < m; k++) {
                    int e = base + k;
                    _fill_one(src[e], dst[e], attr[e], n_coarse, n_nodes);
                }
            }
        }
    }

    // ---- grid barrier: all fills visible ----
    _grid_barrier(nB);

    // ---- phase 2: gather, one warp per node (R7 inner loop, fp32 x) ----
    unsigned lane   = tid & 31;
    unsigned gwarp  = bid * 8 + (tid >> 5);
    unsigned nwarps = nB * 8;

    for (int w = gwarp; w < n_coarse; w += nwarps) {
        int raw_cnt = g_counts[w];
        float2 acc = make_float2(0.f, 0.f);

        if (raw_cnt <= BUCKET_CAP) {
            const int2* __restrict__ b = g_bucket + (unsigned)w * BUCKET_CAP;
            int i = 0;
            for (; i + 4 <= raw_cnt; i += 4) {
                int2 p0 = b[i], p1 = b[i + 1], p2 = b[i + 2], p3 = b[i + 3];
                _acc2(acc, x2, (unsigned)p0.x, __int_as_float(p0.y), lane);
                _acc2(acc, x2, (unsigned)p1.x, __int_as_float(p1.y), lane);
                _acc2(acc, x2, (unsigned)p2.x, __int_as_float(p2.y), lane);
                _acc2(acc, x2, (unsigned)p3.x, __int_as_float(p3.y), lane);
            }
            for (; i < raw_cnt; i++) {
                int2 p = b[i];
                _acc2(acc, x2, (unsigned)p.x, __int_as_float(p.y), lane);
            }
        } else {
            // overflow (statistically never): exact rescan of the edge list
            for (int e = 0; e < num_edges; e++) {
                if (dst[e] == w) {
                    int s = src[e];
                    float wt = attr[e];
                    if ((unsigned)s >= (unsigned)n_nodes) { s = 0; wt = 0.f; }
                    _acc2(acc, x2, (unsigned)s, wt, lane);
                }
            }
        }

        out2[(unsigned)w * 32u + lane] = acc;
        if (lane == 0) g_counts[w] = 0;   // self-reset for next call
    }
}

// ---------- fallback (shapes exceed scratch): atomic scatter, fp32 ----------
__global__ void _zero_out_kernel(float4* __restrict__ out, int n4) {
    int i = blockIdx.x * blockDim.x + threadIdx.x;
    if (i < n4) out[i] = make_float4(0.f, 0.f, 0.f, 0.f);
}

__global__ void __launch_bounds__(256)
_scatter_add_kernel(const float4* __restrict__ x4,
                    const int* __restrict__ src,
                    const int* __restrict__ dst,
                    const float* __restrict__ attr,
                    float* __restrict__ out,
                    int num_edges, int n_nodes, int n_coarse) {
    int t = blockIdx.x * blockDim.x + threadIdx.x;
    int e = t >> 4;
    int c = t & 15;
    if (e >= num_edges) return;
    int s = src[e];
    int d = dst[e];
    float w = attr[e];
    if ((unsigned)s >= (unsigned)n_nodes || (unsigned)d >= (unsigned)n_coarse) return;
    float4 v = x4[(long long)s * 16 + c];
    v.x *= w; v.y *= w; v.z *= w; v.w *= w;
    float* p = out + (long long)d * 64 + c * 4;
    asm volatile("red.global.add.v4.f32 [%0], {%1, %2, %3, %4};"
                 :: "l"(p), "f"(v.x), "f"(v.y), "f"(v.z), "f"(v.w)
                 : "memory");
}

extern "C" void kernel_launch(void* const* d_in, const int* in_sizes, int n_in,
                              void* d_out, int out_size) {
    const float* x    = (const float*)d_in[0];     // [n_nodes, 64] f32
    const int*   eidx = (const int*)d_in[1];       // [2, E] int32
    const float* attr = (const float*)d_in[2];     // [E] f32
    float*       out  = (float*)d_out;             // [n_coarse, 64] f32

    int num_edges = in_sizes[2];
    int n_nodes   = in_sizes[0] / 64;
    int n_coarse  = out_size / 64;
    const int* src = eidx;
    const int* dst = eidx + num_edges;

    if (n_coarse <= MAX_CB && n_nodes <= MAX_NODES) {
        int vec_ok = ((num_edges & 3) == 0) &&
                     ((((unsigned long long)(uintptr_t)eidx) & 15ull) == 0) &&
                     ((((unsigned long long)(uintptr_t)attr) & 15ull) == 0);

        int sms = 148;
        cudaDeviceGetAttribute(&sms, cudaDevAttrMultiProcessorCount, 0);
        int nB = sms * 6;       // launch_bounds(256,6) guarantees residency

        _fused_kernel<<<nB, 256>>>((const float2*)x, src, dst, attr,
                                   (float2*)out,
                                   num_edges, n_coarse, n_nodes, vec_ok);
    } else {
        int n4 = out_size / 4;
        _zero_out_kernel<<<(n4 + 255) / 256, 256>>>((float4*)out, n4);
        long long tt = (long long)num_edges * 16;
        _scatter_add_kernel<<<(int)((tt + 255) / 256), 256>>>(
            (const float4*)x, src, dst, attr, out, num_edges, n_nodes, n_coarse);
    }
}

// round 12
// speedup vs baseline: 1.0499x; 1.0499x over previous
#include <cuda_runtime.h>
#include <cuda_fp16.h>
#include <cstdint>

// out[dst[e]] += edge_attr[e] * x[src[e]],  D=64 f32, indices int32.
// History: R2 scatter 58us (REDG-bound). R4/R6 bucket+gather 47.6us. R7 fp16
// 46.8us. R8/R9 gather-loop variants regressed. R10 fused persistent kernel
// (convert||fill, grid barrier, fp16 gather): 45.5us = best. R11 fp32 gather
// regressed (47.8) -> fp16 gather + hidden convert confirmed valuable.
// R12: R10 base + (a) software-pipelined gather (prefetch next 4 bucket
// entries so meta latency hides under cvt/FMA of current batch), (b) __ldcs
// streaming hint on read-once bucket data.

#define BUCKET_CAP 192           // Poisson(40) over 25K bins: max ~85
#define MAX_CB     32768
#define MAX_NODES  131072

__device__ int      g_counts[MAX_CB];                        // zero-init, self-resetting
__device__ int2     g_bucket[(size_t)MAX_CB * BUCKET_CAP];   // {src, attr bits}
__device__ uint2    g_xh[(size_t)MAX_NODES * 16];            // x as fp16: [node][32] half2
__device__ unsigned g_bar;                                   // monotonic barrier counter

// ---------------- helpers ----------------
__device__ __forceinline__ void _fill_one(int s, int d, float w,
                                          int n_coarse, int n_nodes) {
    if ((unsigned)d >= (unsigned)n_coarse) return;
    if ((unsigned)s >= (unsigned)n_nodes) { s = 0; w = 0.f; }
    int pos = atomicAdd(&g_counts[d], 1);
    if (pos < BUCKET_CAP)
        g_bucket[(unsigned)d * BUCKET_CAP + pos] = make_int2(s, __float_as_int(w));
    // overflow: true total stays in g_counts; gather rescans exactly.
}

__device__ __forceinline__ void _acc2(float2& acc, const __half2* __restrict__ xh2,
                                      unsigned s, float wt, unsigned lane) {
    float2 v = __half22float2(xh2[s * 32u + lane]);
    acc.x = fmaf(wt, v.x, acc.x);
    acc.y = fmaf(wt, v.y, acc.y);
}

// Replay-safe grid barrier: counter only ever increments; each call's blocks
// wait for the next multiple of gridDim.x. Requires all blocks resident.
__device__ __forceinline__ void _grid_barrier(unsigned nB) {
    __threadfence();
    __syncthreads();
    if (threadIdx.x == 0) {
        unsigned arrive;
        asm volatile("atom.add.release.gpu.u32 %0, [%1], 1;"
                     : "=r"(arrive) : "l"(&g_bar) : "memory");
        arrive += 1;
        unsigned target = ((arrive - 1) / nB + 1) * nB;
        unsigned cur;
        do {
            asm volatile("ld.acquire.gpu.u32 %0, [%1];"
                         : "=r"(cur) : "l"(&g_bar) : "memory");
        } while (cur < target);
    }
    __syncthreads();
}

// ---------------- fused persistent kernel ----------------
__global__ void __launch_bounds__(256, 6)
_fused_kernel(const float4* __restrict__ x4,     // x as [n_nodes*16] float4
              const float2* __restrict__ x2,     // fp32 x (overflow path)
              const int* __restrict__ src, const int* __restrict__ dst,
              const float* __restrict__ attr,
              float2* __restrict__ out2,          // [n_coarse, 32] float2
              int num_edges, int n_coarse, int n_nodes, int vec_ok) {
    const unsigned nB  = gridDim.x;
    const unsigned bid = blockIdx.x;
    const unsigned tid = threadIdx.x;

    // ---- phase 1: convert (blocks [0, convB)) || fill (rest) ----
    const unsigned convB = nB / 4;
    if (bid < convB) {
        int n16 = n_nodes * 16;
        for (int t = bid * 256 + tid; t < n16; t += convB * 256) {
            float4 v = x4[t];
            __half2 h0 = __floats2half2_rn(v.x, v.y);
            __half2 h1 = __floats2half2_rn(v.z, v.w);
            uint2 u;
            u.x = *(const unsigned*)&h0;
            u.y = *(const unsigned*)&h1;
            g_xh[t] = u;
        }
    } else {
        const unsigned fB = nB - convB;
        const unsigned fbid = bid - convB;
        int nchunks = (num_edges + 3) / 4;
        for (int ch = fbid * 256 + tid; ch < nchunks; ch += fB * 256) {
            int base = ch * 4;
            if (vec_ok && base + 4 <= num_edges) {
                int4   s4 = *(const int4*)(src + base);
                int4   d4 = *(const int4*)(dst + base);
                float4 w4 = *(const float4*)(attr + base);
                _fill_one(s4.x, d4.x, w4.x, n_coarse, n_nodes);
                _fill_one(s4.y, d4.y, w4.y, n_coarse, n_nodes);
                _fill_one(s4.z, d4.z, w4.z, n_coarse, n_nodes);
                _fill_one(s4.w, d4.w, w4.w, n_coarse, n_nodes);
            } else {
                int m = min(4, num_edges - base);
                for (int k = 0; k < m; k++) {
                    int e = base + k;
                    _fill_one(src[e], dst[e], attr[e], n_coarse, n_nodes);
                }
            }
        }
    }

    // ---- grid barrier: fill + convert complete ----
    _grid_barrier(nB);

    // ---- phase 2: gather, one warp per node, software-pipelined ----
    const __half2* __restrict__ xh2 = (const __half2*)g_xh;
    unsigned lane   = tid & 31;
    unsigned gwarp  = bid * 8 + (tid >> 5);
    unsigned nwarps = nB * 8;

    for (int w = gwarp; w < n_coarse; w += nwarps) {
        int raw_cnt = g_counts[w];
        float2 acc = make_float2(0.f, 0.f);

        if (raw_cnt <= BUCKET_CAP) {
            const int2* __restrict__ b = g_bucket + (unsigned)w * BUCKET_CAP;
            int nfull = raw_cnt & ~3;          // multiple-of-4 part
            int i = 0;
            if (nfull > 0) {
                // prologue: load first batch of metadata (streaming, read-once)
                int2 m0 = __ldcs(b + 0), m1 = __ldcs(b + 1);
                int2 m2 = __ldcs(b + 2), m3 = __ldcs(b + 3);
                for (i = 4; i < nfull; i += 4) {
                    // prefetch next batch before consuming current
                    int2 n0 = __ldcs(b + i),     n1 = __ldcs(b + i + 1);
                    int2 n2 = __ldcs(b + i + 2), n3 = __ldcs(b + i + 3);
                    _acc2(acc, xh2, (unsigned)m0.x, __int_as_float(m0.y), lane);
                    _acc2(acc, xh2, (unsigned)m1.x, __int_as_float(m1.y), lane);
                    _acc2(acc, xh2, (unsigned)m2.x, __int_as_float(m2.y), lane);
                    _acc2(acc, xh2, (unsigned)m3.x, __int_as_float(m3.y), lane);
                    m0 = n0; m1 = n1; m2 = n2; m3 = n3;
                }
                // epilogue for the last full batch
                _acc2(acc, xh2, (unsigned)m0.x, __int_as_float(m0.y), lane);
                _acc2(acc, xh2, (unsigned)m1.x, __int_as_float(m1.y), lane);
                _acc2(acc, xh2, (unsigned)m2.x, __int_as_float(m2.y), lane);
                _acc2(acc, xh2, (unsigned)m3.x, __int_as_float(m3.y), lane);
                i = nfull;
            }
            for (; i < raw_cnt; i++) {
                int2 p = __ldcs(b + i);
                _acc2(acc, xh2, (unsigned)p.x, __int_as_float(p.y), lane);
            }
        } else {
            // overflow (statistically never): exact fp32 rescan
            for (int e = 0; e < num_edges; e++) {
                if (dst[e] == w) {
                    int s = src[e];
                    float wt = attr[e];
                    if ((unsigned)s >= (unsigned)n_nodes) { s = 0; wt = 0.f; }
                    float2 v = x2[(unsigned)s * 32u + lane];
                    acc.x = fmaf(wt, v.x, acc.x);
                    acc.y = fmaf(wt, v.y, acc.y);
                }
            }
        }

        out2[(unsigned)w * 32u + lane] = acc;
        if (lane == 0) g_counts[w] = 0;   // self-reset for next call
    }
}

// ---------- fallback (shapes exceed scratch): atomic scatter, fp32 ----------
__global__ void _zero_out_kernel(float4* __restrict__ out, int n4) {
    int i = blockIdx.x * blockDim.x + threadIdx.x;
    if (i < n4) out[i] = make_float4(0.f, 0.f, 0.f, 0.f);
}

__global__ void __launch_bounds__(256)
_scatter_add_kernel(const float4* __restrict__ x4,
                    const int* __restrict__ src,
                    const int* __restrict__ dst,
                    const float* __restrict__ attr,
                    float* __restrict__ out,
                    int num_edges, int n_nodes, int n_coarse) {
    int t = blockIdx.x * blockDim.x + threadIdx.x;
    int e = t >> 4;
    int c = t & 15;
    if (e >= num_edges) return;
    int s = src[e];
    int d = dst[e];
    float w = attr[e];
    if ((unsigned)s >= (unsigned)n_nodes || (unsigned)d >= (unsigned)n_coarse) return;
    float4 v = x4[(long long)s * 16 + c];
    v.x *= w; v.y *= w; v.z *= w; v.w *= w;
    float* p = out + (long long)d * 64 + c * 4;
    asm volatile("red.global.add.v4.f32 [%0], {%1, %2, %3, %4};"
                 :: "l"(p), "f"(v.x), "f"(v.y), "f"(v.z), "f"(v.w)
                 : "memory");
}

extern "C" void kernel_launch(void* const* d_in, const int* in_sizes, int n_in,
                              void* d_out, int out_size) {
    const float* x    = (const float*)d_in[0];     // [n_nodes, 64] f32
    const int*   eidx = (const int*)d_in[1];       // [2, E] int32
    const float* attr = (const float*)d_in[2];     // [E] f32
    float*       out  = (float*)d_out;             // [n_coarse, 64] f32

    int num_edges = in_sizes[2];
    int n_nodes   = in_sizes[0] / 64;
    int n_coarse  = out_size / 64;
    const int* src = eidx;
    const int* dst = eidx + num_edges;

    if (n_coarse <= MAX_CB && n_nodes <= MAX_NODES) {
        int vec_ok = ((num_edges & 3) == 0) &&
                     ((((unsigned long long)(uintptr_t)eidx) & 15ull) == 0) &&
                     ((((unsigned long long)(uintptr_t)attr) & 15ull) == 0);

        int sms = 148;
        cudaDeviceGetAttribute(&sms, cudaDevAttrMultiProcessorCount, 0);
        int nB = sms * 6;       // launch_bounds(256,6) guarantees residency

        _fused_kernel<<<nB, 256>>>((const float4*)x, (const float2*)x,
                                   src, dst, attr, (float2*)out,
                                   num_edges, n_coarse, n_nodes, vec_ok);
    } else {
        int n4 = out_size / 4;
        _zero_out_kernel<<<(n4 + 255) / 256, 256>>>((float4*)out, n4);
        long long tt = (long long)num_edges * 16;
        _scatter_add_kernel<<<(int)((tt + 255) / 256), 256>>>(
            (const float4*)x, src, dst, attr, out, num_edges, n_nodes, n_coarse);
    }
}